// round 13
// baseline (speedup 1.0000x reference)
#include <cuda_runtime.h>
#include <cuda_fp16.h>
#include <math.h>
#include <stdint.h>

// Problem constants
#define Bq   4
#define Tt   2048
#define Dd   1024
#define Hh   16
#define QKd  64
#define Mrows (Bq*Tt)          // 8192
#define HD   (Hh*QKd)          // 1024
#define GK   1024              // K for every GEMM here

// Scratch (device globals — allocation-free rule)
__device__ __half g_q16 [(size_t)Mrows*HD];
__device__ __half g_kv16[(size_t)Mrows*HD];
__device__ __half g_qh  [(size_t)Mrows*HD];
__device__ __half g_kh  [(size_t)Mrows*HD];
__device__ __half g_vh  [(size_t)Mrows*HD];
__device__ __half g_at  [(size_t)Mrows*HD];
__device__ __half g_wt16[4][(size_t)GK*HD];

// ===========================================================================
// helpers
// ===========================================================================
__device__ __forceinline__ uint32_t smem_u32(const void* p) {
    uint32_t a;
    asm("{ .reg .u64 t; cvta.to.shared.u64 t, %1; cvt.u32.u64 %0, t; }"
        : "=r"(a) : "l"(p));
    return a;
}

__device__ __forceinline__ uint32_t pack_h2(float lo, float hi) {
    __half2 h = __floats2half2_rn(lo, hi);
    return *(uint32_t*)&h;
}

#define CP_ASYNC16(dst_u32, src_ptr) \
    asm volatile("cp.async.cg.shared.global [%0], [%1], 16;" \
                 :: "r"(dst_u32), "l"(src_ptr) : "memory")
#define CP_COMMIT() asm volatile("cp.async.commit_group;" ::: "memory")
#define CP_WAIT1()  asm volatile("cp.async.wait_group 1;" ::: "memory")
#define CP_WAIT0()  asm volatile("cp.async.wait_group 0;" ::: "memory")

#define LDSM4(r0, r1, r2, r3, addr) \
    asm volatile("ldmatrix.sync.aligned.m8n8.x4.shared.b16 {%0,%1,%2,%3}, [%4];" \
                 : "=r"(r0), "=r"(r1), "=r"(r2), "=r"(r3) : "r"(addr))

#define LDSM4T(r0, r1, r2, r3, addr) \
    asm volatile("ldmatrix.sync.aligned.m8n8.x4.trans.shared.b16 {%0,%1,%2,%3}, [%4];" \
                 : "=r"(r0), "=r"(r1), "=r"(r2), "=r"(r3) : "r"(addr))

__device__ __forceinline__ void mma_f16(float* c, const uint32_t* a,
                                        uint32_t b0, uint32_t b1) {
    asm volatile(
        "mma.sync.aligned.m16n8k16.row.col.f32.f16.f16.f32 "
        "{%0,%1,%2,%3}, {%4,%5,%6,%7}, {%8,%9}, {%0,%1,%2,%3};"
        : "+f"(c[0]), "+f"(c[1]), "+f"(c[2]), "+f"(c[3])
        : "r"(a[0]), "r"(a[1]), "r"(a[2]), "r"(a[3]), "r"(b0), "r"(b1));
}

// ===========================================================================
// fp32 -> fp16 input conversion (q, kv)
// ===========================================================================
__global__ void __launch_bounds__(256)
f32_to_f16(const float* __restrict__ s0, const float* __restrict__ s1,
           __half* __restrict__ d0, __half* __restrict__ d1)
{
    const float* s = blockIdx.z ? s1 : s0;
    __half* d      = blockIdx.z ? d1 : d0;
    size_t i = ((size_t)blockIdx.x * 256 + threadIdx.x) * 4;
    float4 v = *(const float4*)(s + i);
    __half2 h0 = __floats2half2_rn(v.x, v.y);
    __half2 h1 = __floats2half2_rn(v.z, v.w);
    uint2 o;
    o.x = *(uint32_t*)&h0;
    o.y = *(uint32_t*)&h1;
    *(uint2*)(d + i) = o;
}

// ===========================================================================
// Fused 4x transpose 1024x1024, fp32 -> fp16 (weights -> K-major fp16 B)
// ===========================================================================
__global__ void __launch_bounds__(256)
transpose4(const float* __restrict__ s0, const float* __restrict__ s1,
           const float* __restrict__ s2, const float* __restrict__ s3,
           __half* __restrict__ d0, __half* __restrict__ d1,
           __half* __restrict__ d2, __half* __restrict__ d3)
{
    const float* in = (blockIdx.z == 0) ? s0 : (blockIdx.z == 1) ? s1
                    : (blockIdx.z == 2) ? s2 : s3;
    __half* out     = (blockIdx.z == 0) ? d0 : (blockIdx.z == 1) ? d1
                    : (blockIdx.z == 2) ? d2 : d3;
    __shared__ float t[32][33];
    int bx = blockIdx.x * 32, by = blockIdx.y * 32;
    #pragma unroll
    for (int i = 0; i < 32; i += 8)
        t[threadIdx.y + i][threadIdx.x] = in[(size_t)(by + threadIdx.y + i) * 1024 + bx + threadIdx.x];
    __syncthreads();
    #pragma unroll
    for (int i = 0; i < 32; i += 8)
        out[(size_t)(bx + threadIdx.y + i) * 1024 + by + threadIdx.x] =
            __float2half_rn(t[threadIdx.x][threadIdx.y + i]);
}

// ===========================================================================
// fp16 m16n8k16 GEMM (multi-problem): C[8192,1024] = A @ BT^T + bias
// 8 warps/CTA, warp tile 32x64, CTA 128x128, BK=64, 3-stage cp.async.
// ===========================================================================
#define LDH 72
#define STG_HALFS (128*LDH)
#define STAGE_BYTES (2*STG_HALFS*2)
#define GEMM_SMEM  (3*STAGE_BYTES)           // 110592

__device__ __forceinline__ void stage_load(uint32_t stageBase, const __half* __restrict__ gA,
                                           const __half* __restrict__ gB, int tid)
{
    #pragma unroll
    for (int it = 0; it < 4; it++) {
        int idx = tid + it * 256;
        int r = idx >> 3, c = idx & 7;
        CP_ASYNC16(stageBase + (r * LDH + c * 8) * 2, gA + (size_t)r * GK + c * 8);
        CP_ASYNC16(stageBase + STG_HALFS * 2 + (r * LDH + c * 8) * 2, gB + (size_t)r * GK + c * 8);
    }
}

__global__ void __launch_bounds__(256, 2)
gemm3(const __half* __restrict__ A0, const __half* __restrict__ A1, const __half* __restrict__ A2,
      const __half* __restrict__ B0, const __half* __restrict__ B1, const __half* __restrict__ B2,
      const float* __restrict__ c0, const float* __restrict__ c1, const float* __restrict__ c2,
      const float* __restrict__ r0, const float* __restrict__ r1,
      const int* __restrict__ p0, const int* __restrict__ p1,
      void* __restrict__ C0, void* __restrict__ C1, void* __restrict__ C2,
      int fuseMask, int halfMask)
{
    extern __shared__ char smc[];
    const uint32_t s32 = smem_u32(smc);

    const int z = blockIdx.z;
    const __half* A    = (z == 0) ? A0 : (z == 1) ? A1 : A2;
    const __half* BT   = (z == 0) ? B0 : (z == 1) ? B1 : B2;
    const float* bias  = (z == 0) ? c0 : (z == 1) ? c1 : c2;
    void* C            = (z == 0) ? C0 : (z == 1) ? C1 : C2;
    const float* rscale = (z == 0) ? r0 : r1;
    const int*   pos    = (z == 0) ? p0 : p1;
    const int FUSE = (fuseMask >> z) & 1;
    const int HOUT = (halfMask >> z) & 1;

    const int tid  = threadIdx.x;
    const int wid  = tid >> 5;
    const int lane = tid & 31;
    const int g    = lane >> 2;
    const int tg   = lane & 3;
    const int wm   = wid & 3;
    const int wn   = wid >> 2;
    const int bm   = blockIdx.y, bn = blockIdx.x;

    const __half* gA = A  + (size_t)(bm * 128) * GK;
    const __half* gB = BT + (size_t)(bn * 128) * GK;

    const int arow  = (lane & 7) + ((lane >> 3) & 1) * 8;
    const int ahoff = (lane >> 4) * 8;
    const int brow  = (lane & 7) + (lane >> 4) * 8;
    const int bhoff = ((lane >> 3) & 1) * 8;
    const uint32_t aOff = ((wm * 32 + arow) * LDH + ahoff) * 2;
    const uint32_t bOff = STG_HALFS * 2 + ((wn * 64 + brow) * LDH + bhoff) * 2;

    float acc[2][8][4];
    #pragma unroll
    for (int mt = 0; mt < 2; mt++)
        #pragma unroll
        for (int j = 0; j < 8; j++)
            #pragma unroll
            for (int r = 0; r < 4; r++) acc[mt][j][r] = 0.f;

    const int NC = GK / 64;

    stage_load(s32,               gA,      gB,      tid); CP_COMMIT();
    stage_load(s32 + STAGE_BYTES, gA + 64, gB + 64, tid); CP_COMMIT();

    int s = 0, sn = 2;
    for (int c = 0; c < NC; c++) {
        if (c + 2 < NC) CP_WAIT1(); else CP_WAIT0();
        __syncthreads();

        if (c + 2 < NC) {
            stage_load(s32 + sn * STAGE_BYTES, gA + (c + 2) * 64, gB + (c + 2) * 64, tid);
            CP_COMMIT();
        }

        const uint32_t aAddr = s32 + s * STAGE_BYTES + aOff;
        const uint32_t bAddr = s32 + s * STAGE_BYTES + bOff;

        #pragma unroll
        for (int ks = 0; ks < 4; ks++) {
            const int ko = ks * 32;
            uint32_t afr[2][4], bfr[8][2];
            LDSM4(afr[0][0], afr[0][1], afr[0][2], afr[0][3], aAddr + ko);
            LDSM4(afr[1][0], afr[1][1], afr[1][2], afr[1][3], aAddr + 16 * LDH * 2 + ko);
            LDSM4(bfr[0][0], bfr[0][1], bfr[1][0], bfr[1][1], bAddr + ko);
            LDSM4(bfr[2][0], bfr[2][1], bfr[3][0], bfr[3][1], bAddr + 16 * LDH * 2 + ko);
            LDSM4(bfr[4][0], bfr[4][1], bfr[5][0], bfr[5][1], bAddr + 32 * LDH * 2 + ko);
            LDSM4(bfr[6][0], bfr[6][1], bfr[7][0], bfr[7][1], bAddr + 48 * LDH * 2 + ko);

            #pragma unroll
            for (int mt = 0; mt < 2; mt++)
                #pragma unroll
                for (int j = 0; j < 8; j++)
                    mma_f16(acc[mt][j], afr[mt], bfr[j][0], bfr[j][1]);
        }

        s = (s == 2) ? 0 : s + 1;
        sn = (sn == 2) ? 0 : sn + 1;
    }

    if (!FUSE) {
        #pragma unroll
        for (int mt = 0; mt < 2; mt++) {
            #pragma unroll
            for (int rr = 0; rr < 2; rr++) {
                int row = bm * 128 + wm * 32 + mt * 16 + g + rr * 8;
                const float* bp = bias + bn * 128 + wn * 64;
                #pragma unroll
                for (int j = 0; j < 8; j++) {
                    int col = j * 8 + 2 * tg;
                    float ox = acc[mt][j][rr * 2 + 0] + bp[col];
                    float oy = acc[mt][j][rr * 2 + 1] + bp[col + 1];
                    if (HOUT) {
                        __half* Ch = (__half*)C;
                        *(__half2*)(Ch + (size_t)row * HD + bn * 128 + wn * 64 + col) =
                            __floats2half2_rn(ox, oy);
                    } else {
                        float2 o; o.x = ox; o.y = oy;
                        *(float2*)((float*)C + (size_t)row * HD + bn * 128 + wn * 64 + col) = o;
                    }
                }
            }
        }
    } else {
        // fused per-head RMSNorm + RoPE. Warp's 64 cols = one full head.
        const int hb = bn * 128 + wn * 64;
        float bsv[8][2], scv[8][2], its[4][2];
        #pragma unroll
        for (int j = 0; j < 8; j++) {
            int hc = j * 8 + 2 * tg;
            bsv[j][0] = bias[hb + hc];     bsv[j][1] = bias[hb + hc + 1];
            scv[j][0] = 1.f + rscale[hc];  scv[j][1] = 1.f + rscale[hc + 1];
        }
        const float kfreq = -0.41523683613691915f;  // -log2(10000)/32
        #pragma unroll
        for (int j = 0; j < 4; j++) {
            int i0 = j * 8 + 2 * tg;
            its[j][0] = exp2f(kfreq * (float)i0);
            its[j][1] = exp2f(kfreq * (float)(i0 + 1));
        }
        #pragma unroll
        for (int mt = 0; mt < 2; mt++) {
            #pragma unroll
            for (int rr = 0; rr < 2; rr++) {
                int row = bm * 128 + wm * 32 + mt * 16 + g + rr * 8;
                float v[8][2], ss = 0.f;
                #pragma unroll
                for (int j = 0; j < 8; j++) {
                    v[j][0] = acc[mt][j][rr * 2 + 0] + bsv[j][0];
                    v[j][1] = acc[mt][j][rr * 2 + 1] + bsv[j][1];
                    ss += v[j][0] * v[j][0] + v[j][1] * v[j][1];
                }
                ss += __shfl_xor_sync(0xffffffffu, ss, 1);
                ss += __shfl_xor_sync(0xffffffffu, ss, 2);
                float rs = rsqrtf(ss * (1.0f / 64.0f) + 1e-6f);
                #pragma unroll
                for (int j = 0; j < 8; j++) {
                    v[j][0] *= rs * scv[j][0];
                    v[j][1] *= rs * scv[j][1];
                }
                float p = (float)pos[row];
                __half* Ch = (__half*)C + (size_t)row * HD + hb;
                #pragma unroll
                for (int j = 0; j < 4; j++) {
                    float y1v[2], y2v[2];
                    #pragma unroll
                    for (int cc = 0; cc < 2; cc++) {
                        float sv, cv;
                        sincosf(p * its[j][cc], &sv, &cv);
                        y1v[cc] = v[j][cc] * cv - v[j + 4][cc] * sv;
                        y2v[cc] = v[j + 4][cc] * cv + v[j][cc] * sv;
                    }
                    int i0 = j * 8 + 2 * tg;
                    *(__half2*)(Ch + i0)      = __floats2half2_rn(y1v[0], y1v[1]);
                    *(__half2*)(Ch + i0 + 32) = __floats2half2_rn(y2v[0], y2v[1]);
                }
            }
        }
    }
}

// ===========================================================================
// Flash attention, all-fp16 operands (fp32 accum + softmax).
// 128-thread CTAs, 64 q-rows, 128-KEY tiles: one softmax pass per 128 keys
// (halves reductions/rescale/barrier overhead per key). 3 CTAs/SM.
// ===========================================================================
#define LDKH 72
#define LDVH 72
#define KSTG_B (128*LDKH*2)              // 18432 B
#define VSTG_B (128*LDVH*2)              // 18432 B
#define FA_SMEM (2*KSTG_B + 2*VSTG_B)    // 73728 B

__global__ void __launch_bounds__(128, 3)
flash_mma(const __half* __restrict__ Qx, const __half* __restrict__ Kx,
          const __half* __restrict__ Vx, const float* __restrict__ hs,
          __half* __restrict__ O)
{
    extern __shared__ char smc[];
    const uint32_t K32 = smem_u32(smc);
    const uint32_t V32 = K32 + 2 * KSTG_B;

    const int tid  = threadIdx.x;
    const int wid  = tid >> 5;        // 0..3
    const int lane = tid & 31;
    const int g    = lane >> 2;
    const int t    = lane & 3;

    const int bh = blockIdx.y;
    const int b  = bh >> 4;
    const int h  = bh & 15;
    const int qt = gridDim.x - 1 - blockIdx.x;   // 64-row q tile, heavy first

    const size_t base = ((size_t)b * Tt * Hh + h) * QKd;
    const int row0 = qt * 64 + wid * 16;
    const int nkt  = (qt >> 1) + 1;              // 128-key tiles

    // K ldmatrix lane offsets (B-frags)
    const int brow  = (lane & 7) + (lane >> 4) * 8;
    const int bhoff = ((lane >> 3) & 1) * 8;
    const uint32_t kBase = K32 + (brow * LDKH + bhoff) * 2;

    // V ldmatrix.trans lane offsets
    const int vmat = lane >> 3;
    const uint32_t vLane = ((uint32_t)((vmat & 1) * 8 + (lane & 7))) * (LDVH * 2)
                         + (uint32_t)((vmat >> 1) * 16);

    // ---- Q fragments (fp16 from global, scaled by (1/8)*log2(e)) ----
    const float QSC = 0.125f * 1.4426950408889634f;
    uint32_t qa[4][4];
    {
        const __half* Qp  = Qx + base + (size_t)(row0 + g) * HD;
        const __half* Qp8 = Qp + (size_t)8 * HD;
        #pragma unroll
        for (int ks = 0; ks < 4; ks++) {
            int k0 = ks * 16;
            float2 v;
            v = __half22float2(*(const __half2*)(Qp  + k0 + 2 * t));
            qa[ks][0] = pack_h2(v.x * QSC, v.y * QSC);
            v = __half22float2(*(const __half2*)(Qp8 + k0 + 2 * t));
            qa[ks][1] = pack_h2(v.x * QSC, v.y * QSC);
            v = __half22float2(*(const __half2*)(Qp  + k0 + 8 + 2 * t));
            qa[ks][2] = pack_h2(v.x * QSC, v.y * QSC);
            v = __half22float2(*(const __half2*)(Qp8 + k0 + 8 + 2 * t));
            qa[ks][3] = pack_h2(v.x * QSC, v.y * QSC);
        }
    }

    // K and V: 128 rows x 64 halfs each; 128 threads x 8 chunks per operand
    #define LOAD_KV(kt_, s_) do {                                            \
        int tok0 = (kt_) * 128;                                              \
        uint32_t kd = K32 + (s_) * KSTG_B;                                   \
        uint32_t vd = V32 + (s_) * VSTG_B;                                   \
        _Pragma("unroll")                                                    \
        for (int it = 0; it < 8; it++) {                                     \
            int idx = tid + it * 128;                                        \
            int j = idx >> 3, fh = idx & 7;                                  \
            const __half* ksrc = Kx + base + (size_t)(tok0 + j) * HD + fh * 8; \
            const __half* vsrc = Vx + base + (size_t)(tok0 + j) * HD + fh * 8; \
            CP_ASYNC16(kd + j * (LDKH * 2) + fh * 16, ksrc);                 \
            CP_ASYNC16(vd + j * (LDVH * 2) + fh * 16, vsrc);                 \
        }                                                                    \
    } while (0)

    LOAD_KV(0, 0);
    CP_COMMIT();

    float oa[8][4];
    #pragma unroll
    for (int i = 0; i < 8; i++)
        #pragma unroll
        for (int r = 0; r < 4; r++) oa[i][r] = 0.f;
    float m0 = -1e30f, m1 = -1e30f, l0 = 0.f, l1 = 0.f;

    for (int kt = 0; kt < nkt; kt++) {
        CP_WAIT0();
        __syncthreads();
        if (kt + 1 < nkt) {
            LOAD_KV(kt + 1, (kt + 1) & 1);
            CP_COMMIT();
        }

        // ---- S = Q K^T over 128 keys (fp16 k16, log2-domain logits) ----
        float sa[16][4];
        #pragma unroll
        for (int j = 0; j < 16; j++)
            #pragma unroll
            for (int r = 0; r < 4; r++) sa[j][r] = 0.f;

        const uint32_t kAddr = kBase + (kt & 1) * KSTG_B;
        #pragma unroll
        for (int ks = 0; ks < 4; ks++) {
            const int ko = ks * 32;
            #pragma unroll
            for (int half = 0; half < 2; half++) {
                uint32_t kb[8][2];
                const uint32_t ka = kAddr + half * (64 * LDKH * 2) + ko;
                LDSM4(kb[0][0], kb[0][1], kb[1][0], kb[1][1], ka);
                LDSM4(kb[2][0], kb[2][1], kb[3][0], kb[3][1], ka + 16 * LDKH * 2);
                LDSM4(kb[4][0], kb[4][1], kb[5][0], kb[5][1], ka + 32 * LDKH * 2);
                LDSM4(kb[6][0], kb[6][1], kb[7][0], kb[7][1], ka + 48 * LDKH * 2);
                #pragma unroll
                for (int nj = 0; nj < 8; nj++)
                    mma_f16(sa[half * 8 + nj], qa[ks], kb[nj][0], kb[nj][1]);
            }
        }

        // ---- causal mask (only near diagonal) ----
        if (kt * 128 + 127 > row0) {
            int r0g = row0 + g, r1g = row0 + 8 + g;
            #pragma unroll
            for (int j = 0; j < 16; j++) {
                int c0 = kt * 128 + j * 8 + 2 * t;
                if (c0     > r0g) sa[j][0] = -1e30f;
                if (c0 + 1 > r0g) sa[j][1] = -1e30f;
                if (c0     > r1g) sa[j][2] = -1e30f;
                if (c0 + 1 > r1g) sa[j][3] = -1e30f;
            }
        }

        // ---- online softmax (exp2 domain), one pass per 128 keys ----
        float rmax0 = -1e30f, rmax1 = -1e30f;
        #pragma unroll
        for (int j = 0; j < 16; j++) {
            rmax0 = fmaxf(rmax0, fmaxf(sa[j][0], sa[j][1]));
            rmax1 = fmaxf(rmax1, fmaxf(sa[j][2], sa[j][3]));
        }
        rmax0 = fmaxf(rmax0, __shfl_xor_sync(0xffffffffu, rmax0, 1));
        rmax0 = fmaxf(rmax0, __shfl_xor_sync(0xffffffffu, rmax0, 2));
        rmax1 = fmaxf(rmax1, __shfl_xor_sync(0xffffffffu, rmax1, 1));
        rmax1 = fmaxf(rmax1, __shfl_xor_sync(0xffffffffu, rmax1, 2));

        float mn0 = fmaxf(m0, rmax0), mn1 = fmaxf(m1, rmax1);
        float corr0 = exp2f(m0 - mn0), corr1 = exp2f(m1 - mn1);
        m0 = mn0; m1 = mn1;

        float sum0 = 0.f, sum1 = 0.f;
        #pragma unroll
        for (int j = 0; j < 16; j++) {
            sa[j][0] = exp2f(sa[j][0] - mn0);
            sa[j][1] = exp2f(sa[j][1] - mn0);
            sa[j][2] = exp2f(sa[j][2] - mn1);
            sa[j][3] = exp2f(sa[j][3] - mn1);
            sum0 += sa[j][0] + sa[j][1];
            sum1 += sa[j][2] + sa[j][3];
        }
        sum0 += __shfl_xor_sync(0xffffffffu, sum0, 1);
        sum0 += __shfl_xor_sync(0xffffffffu, sum0, 2);
        sum1 += __shfl_xor_sync(0xffffffffu, sum1, 1);
        sum1 += __shfl_xor_sync(0xffffffffu, sum1, 2);
        l0 = l0 * corr0 + sum0;
        l1 = l1 * corr1 + sum1;

        #pragma unroll
        for (int i = 0; i < 8; i++) {
            oa[i][0] *= corr0; oa[i][1] *= corr0;
            oa[i][2] *= corr1; oa[i][3] *= corr1;
        }

        // ---- O += P V (fp16 m16n8k16; P C-layout == k16 A-layout) ----
        const uint32_t vAddr = V32 + (kt & 1) * VSTG_B + vLane;
        #pragma unroll
        for (int g4 = 0; g4 < 8; g4++) {
            uint32_t pah[4];
            pah[0] = pack_h2(sa[2*g4][0],   sa[2*g4][1]);
            pah[1] = pack_h2(sa[2*g4][2],   sa[2*g4][3]);
            pah[2] = pack_h2(sa[2*g4+1][0], sa[2*g4+1][1]);
            pah[3] = pack_h2(sa[2*g4+1][2], sa[2*g4+1][3]);
            #pragma unroll
            for (int np = 0; np < 4; np++) {
                uint32_t r0, r1, r2, r3;
                LDSM4T(r0, r1, r2, r3, vAddr + g4 * (16 * LDVH * 2) + np * 32);
                mma_f16(oa[2*np],   pah, r0, r1);
                mma_f16(oa[2*np+1], pah, r2, r3);
            }
        }
    }

    // ---- epilogue: write attention output as fp16 ----
    float hsc = 1.0f + hs[h];
    float inv0 = hsc / l0, inv1 = hsc / l1;
    __half* O0 = O + base + (size_t)(row0 + g) * HD;
    __half* O1 = O + base + (size_t)(row0 + 8 + g) * HD;
    #pragma unroll
    for (int nt = 0; nt < 8; nt++) {
        int col = nt * 8 + 2 * t;
        *(__half2*)(O0 + col) = __floats2half2_rn(oa[nt][0] * inv0, oa[nt][1] * inv0);
        *(__half2*)(O1 + col) = __floats2half2_rn(oa[nt][2] * inv1, oa[nt][3] * inv1);
    }
}

// ---------------------------------------------------------------------------
// launch
// ---------------------------------------------------------------------------
extern "C" void kernel_launch(void* const* d_in, const int* in_sizes, int n_in,
                              void* d_out, int out_size)
{
    const float* q    = (const float*)d_in[0];
    const float* kv   = (const float*)d_in[1];
    const int*   qpos = (const int*)d_in[3];
    const int*   kpos = (const int*)d_in[4];
    const float* Wq   = (const float*)d_in[5];
    const float* bq   = (const float*)d_in[6];
    const float* Wk   = (const float*)d_in[7];
    const float* bk   = (const float*)d_in[8];
    const float* Wv   = (const float*)d_in[9];
    const float* bv   = (const float*)d_in[10];
    const float* qsc  = (const float*)d_in[11];
    const float* ksc  = (const float*)d_in[12];
    const float* hsc  = (const float*)d_in[13];
    const float* Wo   = (const float*)d_in[14];
    const float* bo   = (const float*)d_in[15];
    float* out = (float*)d_out;

    __half *q16, *kv16, *qh, *kh, *vh, *at, *wt;
    cudaGetSymbolAddress((void**)&q16,  g_q16);
    cudaGetSymbolAddress((void**)&kv16, g_kv16);
    cudaGetSymbolAddress((void**)&qh, g_qh);
    cudaGetSymbolAddress((void**)&kh, g_kh);
    cudaGetSymbolAddress((void**)&vh, g_vh);
    cudaGetSymbolAddress((void**)&at, g_at);
    cudaGetSymbolAddress((void**)&wt, g_wt16);
    __half* WqT = wt;
    __half* WkT = wt + (size_t)GK*HD;
    __half* WvT = wt + 2*(size_t)GK*HD;
    __half* WoT = wt + 3*(size_t)GK*HD;

    f32_to_f16<<<dim3((Mrows*HD/4)/256, 1, 2), 256>>>(q, kv, q16, kv16);
    transpose4<<<dim3(32, 32, 4), dim3(32, 8)>>>(Wq, Wk, Wv, Wo, WqT, WkT, WvT, WoT);

    cudaFuncSetAttribute(gemm3, cudaFuncAttributeMaxDynamicSharedMemorySize, GEMM_SMEM);
    cudaFuncSetAttribute(flash_mma, cudaFuncAttributeMaxDynamicSharedMemorySize, FA_SMEM);

    gemm3<<<dim3(HD/128, Mrows/128, 3), 256, GEMM_SMEM>>>(
        q16, kv16, kv16,  WqT, WkT, WvT,  bq, bk, bv,
        qsc, ksc,  qpos, kpos,  qh, kh, vh,  0b011, 0b111);

    flash_mma<<<dim3(Tt/64, Bq*Hh), 128, FA_SMEM>>>(qh, kh, vh, hsc, at);

    gemm3<<<dim3(HD/128, Mrows/128, 1), 256, GEMM_SMEM>>>(
        at, at, at,  WoT, WoT, WoT,  bo, bo, bo,
        qsc, ksc,  qpos, kpos,  out, out, out,  0, 0);
}

// round 14
// speedup vs baseline: 1.0557x; 1.0557x over previous
#include <cuda_runtime.h>
#include <cuda_fp16.h>
#include <math.h>
#include <stdint.h>

// Problem constants
#define Bq   4
#define Tt   2048
#define Dd   1024
#define Hh   16
#define QKd  64
#define Mrows (Bq*Tt)          // 8192
#define HD   (Hh*QKd)          // 1024
#define GK   1024              // K for every GEMM here

// Scratch (device globals — allocation-free rule)
__device__ __half g_q16 [(size_t)Mrows*HD];
__device__ __half g_kv16[(size_t)Mrows*HD];
__device__ __half g_qh  [(size_t)Mrows*HD];
__device__ __half g_kh  [(size_t)Mrows*HD];
__device__ __half g_vh  [(size_t)Mrows*HD];
__device__ __half g_at  [(size_t)Mrows*HD];
__device__ __half g_wt16[4][(size_t)GK*HD];

// ===========================================================================
// helpers
// ===========================================================================
__device__ __forceinline__ uint32_t smem_u32(const void* p) {
    uint32_t a;
    asm("{ .reg .u64 t; cvta.to.shared.u64 t, %1; cvt.u32.u64 %0, t; }"
        : "=r"(a) : "l"(p));
    return a;
}

__device__ __forceinline__ uint32_t pack_h2(float lo, float hi) {
    __half2 h = __floats2half2_rn(lo, hi);
    return *(uint32_t*)&h;
}

#define CP_ASYNC16(dst_u32, src_ptr) \
    asm volatile("cp.async.cg.shared.global [%0], [%1], 16;" \
                 :: "r"(dst_u32), "l"(src_ptr) : "memory")
#define CP_COMMIT() asm volatile("cp.async.commit_group;" ::: "memory")
#define CP_WAIT1()  asm volatile("cp.async.wait_group 1;" ::: "memory")
#define CP_WAIT0()  asm volatile("cp.async.wait_group 0;" ::: "memory")

#define LDSM4(r0, r1, r2, r3, addr) \
    asm volatile("ldmatrix.sync.aligned.m8n8.x4.shared.b16 {%0,%1,%2,%3}, [%4];" \
                 : "=r"(r0), "=r"(r1), "=r"(r2), "=r"(r3) : "r"(addr))

#define LDSM4T(r0, r1, r2, r3, addr) \
    asm volatile("ldmatrix.sync.aligned.m8n8.x4.trans.shared.b16 {%0,%1,%2,%3}, [%4];" \
                 : "=r"(r0), "=r"(r1), "=r"(r2), "=r"(r3) : "r"(addr))

__device__ __forceinline__ void mma_f16(float* c, const uint32_t* a,
                                        uint32_t b0, uint32_t b1) {
    asm volatile(
        "mma.sync.aligned.m16n8k16.row.col.f32.f16.f16.f32 "
        "{%0,%1,%2,%3}, {%4,%5,%6,%7}, {%8,%9}, {%0,%1,%2,%3};"
        : "+f"(c[0]), "+f"(c[1]), "+f"(c[2]), "+f"(c[3])
        : "r"(a[0]), "r"(a[1]), "r"(a[2]), "r"(a[3]), "r"(b0), "r"(b1));
}

// ===========================================================================
// fp32 -> fp16 input conversion (q, kv)
// ===========================================================================
__global__ void __launch_bounds__(256)
f32_to_f16(const float* __restrict__ s0, const float* __restrict__ s1,
           __half* __restrict__ d0, __half* __restrict__ d1)
{
    const float* s = blockIdx.z ? s1 : s0;
    __half* d      = blockIdx.z ? d1 : d0;
    size_t i = ((size_t)blockIdx.x * 256 + threadIdx.x) * 4;
    float4 v = *(const float4*)(s + i);
    __half2 h0 = __floats2half2_rn(v.x, v.y);
    __half2 h1 = __floats2half2_rn(v.z, v.w);
    uint2 o;
    o.x = *(uint32_t*)&h0;
    o.y = *(uint32_t*)&h1;
    *(uint2*)(d + i) = o;
}

// ===========================================================================
// Fused 4x transpose 1024x1024, fp32 -> fp16 (weights -> K-major fp16 B)
// ===========================================================================
__global__ void __launch_bounds__(256)
transpose4(const float* __restrict__ s0, const float* __restrict__ s1,
           const float* __restrict__ s2, const float* __restrict__ s3,
           __half* __restrict__ d0, __half* __restrict__ d1,
           __half* __restrict__ d2, __half* __restrict__ d3)
{
    const float* in = (blockIdx.z == 0) ? s0 : (blockIdx.z == 1) ? s1
                    : (blockIdx.z == 2) ? s2 : s3;
    __half* out     = (blockIdx.z == 0) ? d0 : (blockIdx.z == 1) ? d1
                    : (blockIdx.z == 2) ? d2 : d3;
    __shared__ float t[32][33];
    int bx = blockIdx.x * 32, by = blockIdx.y * 32;
    #pragma unroll
    for (int i = 0; i < 32; i += 8)
        t[threadIdx.y + i][threadIdx.x] = in[(size_t)(by + threadIdx.y + i) * 1024 + bx + threadIdx.x];
    __syncthreads();
    #pragma unroll
    for (int i = 0; i < 32; i += 8)
        out[(size_t)(bx + threadIdx.y + i) * 1024 + by + threadIdx.x] =
            __float2half_rn(t[threadIdx.x][threadIdx.y + i]);
}

// ===========================================================================
// fp16 m16n8k16 GEMM (multi-problem): C[8192,1024] = A @ BT^T + bias
// 8 warps/CTA, warp tile 32x64, CTA 128x128, BK=64, 3-stage cp.async.
// ===========================================================================
#define LDH 72
#define STG_HALFS (128*LDH)
#define STAGE_BYTES (2*STG_HALFS*2)
#define GEMM_SMEM  (3*STAGE_BYTES)           // 110592

__device__ __forceinline__ void stage_load(uint32_t stageBase, const __half* __restrict__ gA,
                                           const __half* __restrict__ gB, int tid)
{
    #pragma unroll
    for (int it = 0; it < 4; it++) {
        int idx = tid + it * 256;
        int r = idx >> 3, c = idx & 7;
        CP_ASYNC16(stageBase + (r * LDH + c * 8) * 2, gA + (size_t)r * GK + c * 8);
        CP_ASYNC16(stageBase + STG_HALFS * 2 + (r * LDH + c * 8) * 2, gB + (size_t)r * GK + c * 8);
    }
}

__global__ void __launch_bounds__(256, 2)
gemm3(const __half* __restrict__ A0, const __half* __restrict__ A1, const __half* __restrict__ A2,
      const __half* __restrict__ B0, const __half* __restrict__ B1, const __half* __restrict__ B2,
      const float* __restrict__ c0, const float* __restrict__ c1, const float* __restrict__ c2,
      const float* __restrict__ r0, const float* __restrict__ r1,
      const int* __restrict__ p0, const int* __restrict__ p1,
      void* __restrict__ C0, void* __restrict__ C1, void* __restrict__ C2,
      int fuseMask, int halfMask)
{
    extern __shared__ char smc[];
    const uint32_t s32 = smem_u32(smc);

    const int z = blockIdx.z;
    const __half* A    = (z == 0) ? A0 : (z == 1) ? A1 : A2;
    const __half* BT   = (z == 0) ? B0 : (z == 1) ? B1 : B2;
    const float* bias  = (z == 0) ? c0 : (z == 1) ? c1 : c2;
    void* C            = (z == 0) ? C0 : (z == 1) ? C1 : C2;
    const float* rscale = (z == 0) ? r0 : r1;
    const int*   pos    = (z == 0) ? p0 : p1;
    const int FUSE = (fuseMask >> z) & 1;
    const int HOUT = (halfMask >> z) & 1;

    const int tid  = threadIdx.x;
    const int wid  = tid >> 5;
    const int lane = tid & 31;
    const int g    = lane >> 2;
    const int tg   = lane & 3;
    const int wm   = wid & 3;
    const int wn   = wid >> 2;
    const int bm   = blockIdx.y, bn = blockIdx.x;

    const __half* gA = A  + (size_t)(bm * 128) * GK;
    const __half* gB = BT + (size_t)(bn * 128) * GK;

    const int arow  = (lane & 7) + ((lane >> 3) & 1) * 8;
    const int ahoff = (lane >> 4) * 8;
    const int brow  = (lane & 7) + (lane >> 4) * 8;
    const int bhoff = ((lane >> 3) & 1) * 8;
    const uint32_t aOff = ((wm * 32 + arow) * LDH + ahoff) * 2;
    const uint32_t bOff = STG_HALFS * 2 + ((wn * 64 + brow) * LDH + bhoff) * 2;

    float acc[2][8][4];
    #pragma unroll
    for (int mt = 0; mt < 2; mt++)
        #pragma unroll
        for (int j = 0; j < 8; j++)
            #pragma unroll
            for (int r = 0; r < 4; r++) acc[mt][j][r] = 0.f;

    const int NC = GK / 64;

    stage_load(s32,               gA,      gB,      tid); CP_COMMIT();
    stage_load(s32 + STAGE_BYTES, gA + 64, gB + 64, tid); CP_COMMIT();

    int s = 0, sn = 2;
    for (int c = 0; c < NC; c++) {
        if (c + 2 < NC) CP_WAIT1(); else CP_WAIT0();
        __syncthreads();

        if (c + 2 < NC) {
            stage_load(s32 + sn * STAGE_BYTES, gA + (c + 2) * 64, gB + (c + 2) * 64, tid);
            CP_COMMIT();
        }

        const uint32_t aAddr = s32 + s * STAGE_BYTES + aOff;
        const uint32_t bAddr = s32 + s * STAGE_BYTES + bOff;

        #pragma unroll
        for (int ks = 0; ks < 4; ks++) {
            const int ko = ks * 32;
            uint32_t afr[2][4], bfr[8][2];
            LDSM4(afr[0][0], afr[0][1], afr[0][2], afr[0][3], aAddr + ko);
            LDSM4(afr[1][0], afr[1][1], afr[1][2], afr[1][3], aAddr + 16 * LDH * 2 + ko);
            LDSM4(bfr[0][0], bfr[0][1], bfr[1][0], bfr[1][1], bAddr + ko);
            LDSM4(bfr[2][0], bfr[2][1], bfr[3][0], bfr[3][1], bAddr + 16 * LDH * 2 + ko);
            LDSM4(bfr[4][0], bfr[4][1], bfr[5][0], bfr[5][1], bAddr + 32 * LDH * 2 + ko);
            LDSM4(bfr[6][0], bfr[6][1], bfr[7][0], bfr[7][1], bAddr + 48 * LDH * 2 + ko);

            #pragma unroll
            for (int mt = 0; mt < 2; mt++)
                #pragma unroll
                for (int j = 0; j < 8; j++)
                    mma_f16(acc[mt][j], afr[mt], bfr[j][0], bfr[j][1]);
        }

        s = (s == 2) ? 0 : s + 1;
        sn = (sn == 2) ? 0 : sn + 1;
    }

    if (!FUSE) {
        #pragma unroll
        for (int mt = 0; mt < 2; mt++) {
            #pragma unroll
            for (int rr = 0; rr < 2; rr++) {
                int row = bm * 128 + wm * 32 + mt * 16 + g + rr * 8;
                const float* bp = bias + bn * 128 + wn * 64;
                #pragma unroll
                for (int j = 0; j < 8; j++) {
                    int col = j * 8 + 2 * tg;
                    float ox = acc[mt][j][rr * 2 + 0] + bp[col];
                    float oy = acc[mt][j][rr * 2 + 1] + bp[col + 1];
                    if (HOUT) {
                        __half* Ch = (__half*)C;
                        *(__half2*)(Ch + (size_t)row * HD + bn * 128 + wn * 64 + col) =
                            __floats2half2_rn(ox, oy);
                    } else {
                        float2 o; o.x = ox; o.y = oy;
                        *(float2*)((float*)C + (size_t)row * HD + bn * 128 + wn * 64 + col) = o;
                    }
                }
            }
        }
    } else {
        // fused per-head RMSNorm + RoPE. Warp's 64 cols = one full head.
        const int hb = bn * 128 + wn * 64;
        float bsv[8][2], scv[8][2], its[4][2];
        #pragma unroll
        for (int j = 0; j < 8; j++) {
            int hc = j * 8 + 2 * tg;
            bsv[j][0] = bias[hb + hc];     bsv[j][1] = bias[hb + hc + 1];
            scv[j][0] = 1.f + rscale[hc];  scv[j][1] = 1.f + rscale[hc + 1];
        }
        const float kfreq = -0.41523683613691915f;  // -log2(10000)/32
        #pragma unroll
        for (int j = 0; j < 4; j++) {
            int i0 = j * 8 + 2 * tg;
            its[j][0] = exp2f(kfreq * (float)i0);
            its[j][1] = exp2f(kfreq * (float)(i0 + 1));
        }
        #pragma unroll
        for (int mt = 0; mt < 2; mt++) {
            #pragma unroll
            for (int rr = 0; rr < 2; rr++) {
                int row = bm * 128 + wm * 32 + mt * 16 + g + rr * 8;
                float v[8][2], ss = 0.f;
                #pragma unroll
                for (int j = 0; j < 8; j++) {
                    v[j][0] = acc[mt][j][rr * 2 + 0] + bsv[j][0];
                    v[j][1] = acc[mt][j][rr * 2 + 1] + bsv[j][1];
                    ss += v[j][0] * v[j][0] + v[j][1] * v[j][1];
                }
                ss += __shfl_xor_sync(0xffffffffu, ss, 1);
                ss += __shfl_xor_sync(0xffffffffu, ss, 2);
                float rs = rsqrtf(ss * (1.0f / 64.0f) + 1e-6f);
                #pragma unroll
                for (int j = 0; j < 8; j++) {
                    v[j][0] *= rs * scv[j][0];
                    v[j][1] *= rs * scv[j][1];
                }
                float p = (float)pos[row];
                __half* Ch = (__half*)C + (size_t)row * HD + hb;
                #pragma unroll
                for (int j = 0; j < 4; j++) {
                    float y1v[2], y2v[2];
                    #pragma unroll
                    for (int cc = 0; cc < 2; cc++) {
                        float sv, cv;
                        sincosf(p * its[j][cc], &sv, &cv);
                        y1v[cc] = v[j][cc] * cv - v[j + 4][cc] * sv;
                        y2v[cc] = v[j + 4][cc] * cv + v[j][cc] * sv;
                    }
                    int i0 = j * 8 + 2 * tg;
                    *(__half2*)(Ch + i0)      = __floats2half2_rn(y1v[0], y1v[1]);
                    *(__half2*)(Ch + i0 + 32) = __floats2half2_rn(y2v[0], y2v[1]);
                }
            }
        }
    }
}

// ===========================================================================
// Flash attention, all-fp16 operands, MAX-FREE softmax:
// RMSNorm guarantees |q|=|k|=8, so |log2-logit| <= 11.55 -> exp2(s) <= 3005
// (fp16-safe, fp32-sum-safe). No max reduction, no rescaling, no shfl.
// Row sums come free from an extra MMA against a constant ones B-fragment.
// 128-thread CTAs, 64 q-rows, 64-key double-buffered tiles, 4 CTAs/SM.
// ===========================================================================
#define LDKH 72
#define LDVH 72
#define KSTG_B (64*LDKH*2)               // 9216 B
#define VSTG_B (64*LDVH*2)               // 9216 B
#define FA_SMEM (2*KSTG_B + 2*VSTG_B)    // 36864 B
#define ONES_H2 0x3C003C00u              // (1.0h, 1.0h)

__global__ void __launch_bounds__(128, 4)
flash_mma(const __half* __restrict__ Qx, const __half* __restrict__ Kx,
          const __half* __restrict__ Vx, const float* __restrict__ hs,
          __half* __restrict__ O)
{
    extern __shared__ char smc[];
    const uint32_t K32 = smem_u32(smc);
    const uint32_t V32 = K32 + 2 * KSTG_B;

    const int tid  = threadIdx.x;
    const int wid  = tid >> 5;        // 0..3
    const int lane = tid & 31;
    const int g    = lane >> 2;
    const int t    = lane & 3;

    const int bh = blockIdx.y;
    const int b  = bh >> 4;
    const int h  = bh & 15;
    const int qt = gridDim.x - 1 - blockIdx.x;   // 64-row q tile, heavy first

    const size_t base = ((size_t)b * Tt * Hh + h) * QKd;
    const int row0 = qt * 64 + wid * 16;
    const int nkt  = qt + 1;

    // K ldmatrix lane offsets (B-frags)
    const int brow  = (lane & 7) + (lane >> 4) * 8;
    const int bhoff = ((lane >> 3) & 1) * 8;
    const uint32_t kBase = K32 + (brow * LDKH + bhoff) * 2;

    // V ldmatrix.trans lane offsets
    const int vmat = lane >> 3;
    const uint32_t vLane = ((uint32_t)((vmat & 1) * 8 + (lane & 7))) * (LDVH * 2)
                         + (uint32_t)((vmat >> 1) * 16);

    // ---- Q fragments (fp16 from global, scaled by (1/8)*log2(e)) ----
    const float QSC = 0.125f * 1.4426950408889634f;
    uint32_t qa[4][4];
    {
        const __half* Qp  = Qx + base + (size_t)(row0 + g) * HD;
        const __half* Qp8 = Qp + (size_t)8 * HD;
        #pragma unroll
        for (int ks = 0; ks < 4; ks++) {
            int k0 = ks * 16;
            float2 v;
            v = __half22float2(*(const __half2*)(Qp  + k0 + 2 * t));
            qa[ks][0] = pack_h2(v.x * QSC, v.y * QSC);
            v = __half22float2(*(const __half2*)(Qp8 + k0 + 2 * t));
            qa[ks][1] = pack_h2(v.x * QSC, v.y * QSC);
            v = __half22float2(*(const __half2*)(Qp  + k0 + 8 + 2 * t));
            qa[ks][2] = pack_h2(v.x * QSC, v.y * QSC);
            v = __half22float2(*(const __half2*)(Qp8 + k0 + 8 + 2 * t));
            qa[ks][3] = pack_h2(v.x * QSC, v.y * QSC);
        }
    }

    #define LOAD_KV(kt_, s_) do {                                            \
        int tok0 = (kt_) * 64;                                               \
        uint32_t kd = K32 + (s_) * KSTG_B;                                   \
        uint32_t vd = V32 + (s_) * VSTG_B;                                   \
        _Pragma("unroll")                                                    \
        for (int it = 0; it < 4; it++) {                                     \
            int idx = tid + it * 128;                                        \
            int j = idx >> 3, fh = idx & 7;                                  \
            const __half* ksrc = Kx + base + (size_t)(tok0 + j) * HD + fh * 8; \
            const __half* vsrc = Vx + base + (size_t)(tok0 + j) * HD + fh * 8; \
            CP_ASYNC16(kd + j * (LDKH * 2) + fh * 16, ksrc);                 \
            CP_ASYNC16(vd + j * (LDVH * 2) + fh * 16, vsrc);                 \
        }                                                                    \
    } while (0)

    LOAD_KV(0, 0);
    CP_COMMIT();

    float oa[8][4];
    #pragma unroll
    for (int i = 0; i < 8; i++)
        #pragma unroll
        for (int r = 0; r < 4; r++) oa[i][r] = 0.f;
    float ll[4] = {0.f, 0.f, 0.f, 0.f};   // row sums via ones-MMA

    for (int kt = 0; kt < nkt; kt++) {
        CP_WAIT0();
        __syncthreads();
        if (kt + 1 < nkt) {
            LOAD_KV(kt + 1, (kt + 1) & 1);
            CP_COMMIT();
        }

        // ---- S = Q K^T (fp16 k16, log2-domain logits) ----
        float sa[8][4];
        #pragma unroll
        for (int j = 0; j < 8; j++)
            #pragma unroll
            for (int r = 0; r < 4; r++) sa[j][r] = 0.f;

        const uint32_t kAddr = kBase + (kt & 1) * KSTG_B;
        #pragma unroll
        for (int ks = 0; ks < 4; ks++) {
            const int ko = ks * 32;
            uint32_t kb[8][2];
            LDSM4(kb[0][0], kb[0][1], kb[1][0], kb[1][1], kAddr + ko);
            LDSM4(kb[2][0], kb[2][1], kb[3][0], kb[3][1], kAddr + 16 * LDKH * 2 + ko);
            LDSM4(kb[4][0], kb[4][1], kb[5][0], kb[5][1], kAddr + 32 * LDKH * 2 + ko);
            LDSM4(kb[6][0], kb[6][1], kb[7][0], kb[7][1], kAddr + 48 * LDKH * 2 + ko);
            #pragma unroll
            for (int nj = 0; nj < 8; nj++)
                mma_f16(sa[nj], qa[ks], kb[nj][0], kb[nj][1]);
        }

        // ---- causal mask (exp2f(-1e30) == 0) ----
        if (kt * 64 + 63 > row0) {
            int r0g = row0 + g, r1g = row0 + 8 + g;
            #pragma unroll
            for (int j = 0; j < 8; j++) {
                int c0 = kt * 64 + j * 8 + 2 * t;
                if (c0     > r0g) sa[j][0] = -1e30f;
                if (c0 + 1 > r0g) sa[j][1] = -1e30f;
                if (c0     > r1g) sa[j][2] = -1e30f;
                if (c0 + 1 > r1g) sa[j][3] = -1e30f;
            }
        }

        // ---- unnormalized P = exp2(S); bounded <= ~3005 (fp16-safe) ----
        #pragma unroll
        for (int j = 0; j < 8; j++) {
            sa[j][0] = exp2f(sa[j][0]);
            sa[j][1] = exp2f(sa[j][1]);
            sa[j][2] = exp2f(sa[j][2]);
            sa[j][3] = exp2f(sa[j][3]);
        }

        // ---- O += P V; l += P 1  (fp16 m16n8k16, no shuffles anywhere) ----
        const uint32_t vAddr = V32 + (kt & 1) * VSTG_B + vLane;
        #pragma unroll
        for (int g4 = 0; g4 < 4; g4++) {
            uint32_t pah[4];
            pah[0] = pack_h2(sa[2*g4][0],   sa[2*g4][1]);
            pah[1] = pack_h2(sa[2*g4][2],   sa[2*g4][3]);
            pah[2] = pack_h2(sa[2*g4+1][0], sa[2*g4+1][1]);
            pah[3] = pack_h2(sa[2*g4+1][2], sa[2*g4+1][3]);
            #pragma unroll
            for (int np = 0; np < 4; np++) {
                uint32_t r0, r1, r2, r3;
                LDSM4T(r0, r1, r2, r3, vAddr + g4 * (16 * LDVH * 2) + np * 32);
                mma_f16(oa[2*np],   pah, r0, r1);
                mma_f16(oa[2*np+1], pah, r2, r3);
            }
            mma_f16(ll, pah, ONES_H2, ONES_H2);   // row sums, free via tensor
        }
    }

    // ---- epilogue: normalize by ll (all quad lanes identical), fp16 out ----
    float hsc = 1.0f + hs[h];
    float inv0 = hsc / ll[0], inv1 = hsc / ll[2];
    __half* O0 = O + base + (size_t)(row0 + g) * HD;
    __half* O1 = O + base + (size_t)(row0 + 8 + g) * HD;
    #pragma unroll
    for (int nt = 0; nt < 8; nt++) {
        int col = nt * 8 + 2 * t;
        *(__half2*)(O0 + col) = __floats2half2_rn(oa[nt][0] * inv0, oa[nt][1] * inv0);
        *(__half2*)(O1 + col) = __floats2half2_rn(oa[nt][2] * inv1, oa[nt][3] * inv1);
    }
}

// ---------------------------------------------------------------------------
// launch
// ---------------------------------------------------------------------------
extern "C" void kernel_launch(void* const* d_in, const int* in_sizes, int n_in,
                              void* d_out, int out_size)
{
    const float* q    = (const float*)d_in[0];
    const float* kv   = (const float*)d_in[1];
    const int*   qpos = (const int*)d_in[3];
    const int*   kpos = (const int*)d_in[4];
    const float* Wq   = (const float*)d_in[5];
    const float* bq   = (const float*)d_in[6];
    const float* Wk   = (const float*)d_in[7];
    const float* bk   = (const float*)d_in[8];
    const float* Wv   = (const float*)d_in[9];
    const float* bv   = (const float*)d_in[10];
    const float* qsc  = (const float*)d_in[11];
    const float* ksc  = (const float*)d_in[12];
    const float* hsc  = (const float*)d_in[13];
    const float* Wo   = (const float*)d_in[14];
    const float* bo   = (const float*)d_in[15];
    float* out = (float*)d_out;

    __half *q16, *kv16, *qh, *kh, *vh, *at, *wt;
    cudaGetSymbolAddress((void**)&q16,  g_q16);
    cudaGetSymbolAddress((void**)&kv16, g_kv16);
    cudaGetSymbolAddress((void**)&qh, g_qh);
    cudaGetSymbolAddress((void**)&kh, g_kh);
    cudaGetSymbolAddress((void**)&vh, g_vh);
    cudaGetSymbolAddress((void**)&at, g_at);
    cudaGetSymbolAddress((void**)&wt, g_wt16);
    __half* WqT = wt;
    __half* WkT = wt + (size_t)GK*HD;
    __half* WvT = wt + 2*(size_t)GK*HD;
    __half* WoT = wt + 3*(size_t)GK*HD;

    f32_to_f16<<<dim3((Mrows*HD/4)/256, 1, 2), 256>>>(q, kv, q16, kv16);
    transpose4<<<dim3(32, 32, 4), dim3(32, 8)>>>(Wq, Wk, Wv, Wo, WqT, WkT, WvT, WoT);

    cudaFuncSetAttribute(gemm3, cudaFuncAttributeMaxDynamicSharedMemorySize, GEMM_SMEM);
    cudaFuncSetAttribute(flash_mma, cudaFuncAttributeMaxDynamicSharedMemorySize, FA_SMEM);

    gemm3<<<dim3(HD/128, Mrows/128, 3), 256, GEMM_SMEM>>>(
        q16, kv16, kv16,  WqT, WkT, WvT,  bq, bk, bv,
        qsc, ksc,  qpos, kpos,  qh, kh, vh,  0b011, 0b111);

    flash_mma<<<dim3(Tt/64, Bq*Hh), 128, FA_SMEM>>>(qh, kh, vh, hsc, at);

    gemm3<<<dim3(HD/128, Mrows/128, 1), 256, GEMM_SMEM>>>(
        at, at, at,  WoT, WoT, WoT,  bo, bo, bo,
        qsc, ksc,  qpos, kpos,  out, out, out,  0, 0);
}